// round 1
// baseline (speedup 1.0000x reference)
#include <cuda_runtime.h>

#define NN   50000
#define DD   64
#define LL   3
#define OUTN 16
#define EE   800000
#define FCB  1024   // blocks for FC partial reduction

// ---------------- static device scratch (no allocations allowed) ----------------
__device__ int   g_deg_out[NN];
__device__ int   g_deg_in[NN];
__device__ float g_norm_src[NN];
__device__ float g_norm_dst[NN];
__device__ int   g_rowptr[NN + 1];
__device__ int   g_cursor[NN];
__device__ int   g_col[EE];
__device__ float g_x0[NN * DD];
__device__ float g_x1[NN * DD];
__device__ float g_agg[NN * DD];
__device__ float g_partial[FCB * OUTN];

// ---------------- degree init: self-loop contributes 1 to both degrees ----------
__global__ void k_init_deg(int n) {
    int i = blockIdx.x * blockDim.x + threadIdx.x;
    if (i < n) { g_deg_out[i] = 1; g_deg_in[i] = 1; }
}

// ---------------- edge degree histogram (int atomics, cheap) --------------------
__global__ void k_count(const int* __restrict__ src, const int* __restrict__ dst, int e) {
    int i = blockIdx.x * blockDim.x + threadIdx.x;
    if (i < e) {
        atomicAdd(&g_deg_out[src[i]], 1);
        atomicAdd(&g_deg_in[dst[i]], 1);
    }
}

__global__ void k_norm(int n) {
    int i = blockIdx.x * blockDim.x + threadIdx.x;
    if (i < n) {
        g_norm_src[i] = rsqrtf((float)g_deg_out[i]);
        g_norm_dst[i] = rsqrtf((float)g_deg_in[i]);
    }
}

// ---------------- exclusive scan of (deg_in - 1) -> rowptr, cursor --------------
// One block of 1024 threads; each thread owns a contiguous chunk.
__global__ void k_scan(int n, int e) {
    __shared__ int s_sums[1024];
    int t = threadIdx.x;
    int chunk = (n + 1023) / 1024;
    int lo = t * chunk;
    int hi = lo + chunk; if (hi > n) hi = n;

    int s = 0;
    for (int i = lo; i < hi; i++) s += g_deg_in[i] - 1;
    s_sums[t] = s;
    __syncthreads();

    // Hillis-Steele inclusive scan over 1024 partials
    for (int off = 1; off < 1024; off <<= 1) {
        int v = (t >= off) ? s_sums[t - off] : 0;
        __syncthreads();
        s_sums[t] += v;
        __syncthreads();
    }
    int run = (t == 0) ? 0 : s_sums[t - 1];
    for (int i = lo; i < hi; i++) {
        g_rowptr[i] = run;
        g_cursor[i] = run;
        run += g_deg_in[i] - 1;
    }
    if (t == 0) g_rowptr[n] = e;
}

// ---------------- CSR scatter (by dst) ------------------------------------------
__global__ void k_scatter(const int* __restrict__ src, const int* __restrict__ dst, int e) {
    int i = blockIdx.x * blockDim.x + threadIdx.x;
    if (i < e) {
        int d = dst[i];
        int pos = atomicAdd(&g_cursor[d], 1);
        g_col[pos] = src[i];
    }
}

// ---------------- SpMM: agg[n] = norm_dst[n] * sum_{s in in(n)} x[s]*norm_src[s] --
// Warp per node, float2 per lane (256B row per warp), 4-way edge unroll for MLP.
// Self loop folded in as the accumulator init.
__global__ void k_spmm(const float* __restrict__ xin, float* __restrict__ aggout, int n) {
    int gw = (blockIdx.x * blockDim.x + threadIdx.x) >> 5;
    int lane = threadIdx.x & 31;
    int nwarps = (gridDim.x * blockDim.x) >> 5;

    for (int node = gw; node < n; node += nwarps) {
        int rs = g_rowptr[node];
        int re = g_rowptr[node + 1];

        float2 v = ((const float2*)(xin + (size_t)node * DD))[lane];
        float ns = g_norm_src[node];
        float ax = v.x * ns;
        float ay = v.y * ns;

        int ee = rs;
        for (; ee + 4 <= re; ee += 4) {
            int s0 = g_col[ee + 0];
            int s1 = g_col[ee + 1];
            int s2 = g_col[ee + 2];
            int s3 = g_col[ee + 3];
            float w0 = g_norm_src[s0];
            float w1 = g_norm_src[s1];
            float w2 = g_norm_src[s2];
            float w3 = g_norm_src[s3];
            float2 v0 = ((const float2*)(xin + (size_t)s0 * DD))[lane];
            float2 v1 = ((const float2*)(xin + (size_t)s1 * DD))[lane];
            float2 v2 = ((const float2*)(xin + (size_t)s2 * DD))[lane];
            float2 v3 = ((const float2*)(xin + (size_t)s3 * DD))[lane];
            ax += v0.x * w0 + v1.x * w1 + v2.x * w2 + v3.x * w3;
            ay += v0.y * w0 + v1.y * w1 + v2.y * w2 + v3.y * w3;
        }
        for (; ee < re; ee++) {
            int s0 = g_col[ee];
            float w0 = g_norm_src[s0];
            float2 v0 = ((const float2*)(xin + (size_t)s0 * DD))[lane];
            ax += v0.x * w0;
            ay += v0.y * w0;
        }

        float nd = g_norm_dst[node];
        float2 o; o.x = ax * nd; o.y = ay * nd;
        ((float2*)(aggout + (size_t)node * DD))[lane] = o;
    }
}

// ---------------- dense: xout = relu(agg @ W + b) --------------------------------
// 256 threads: j = tid&63 (output feature), sg = tid>>6 (node subgroup of 8).
// 32-node tile per block; W smem read amortized over 8 nodes per thread.
__global__ void k_gemm(const float* __restrict__ agg, float* __restrict__ xout,
                       const float* __restrict__ W, const float* __restrict__ B, int n) {
    __shared__ float sW[DD * DD];
    __shared__ float sB[DD];
    __shared__ float sA[32 * DD];

    int tid = threadIdx.x;
    for (int i = tid; i < DD * DD; i += 256) sW[i] = W[i];
    if (tid < DD) sB[tid] = B[tid];

    int j  = tid & 63;
    int sg = tid >> 6;

    int base = blockIdx.x * 32;
    // load 32x64 agg tile
    __syncthreads();
    for (int i = tid; i < 32 * DD; i += 256) {
        int node = base + (i >> 6);
        sA[i] = (node < n) ? agg[(size_t)base * DD + i] : 0.f;
    }
    __syncthreads();

    float acc[8];
#pragma unroll
    for (int m = 0; m < 8; m++) acc[m] = sB[j];

#pragma unroll 4
    for (int k = 0; k < DD; k++) {
        float w = sW[k * DD + j];
#pragma unroll
        for (int m = 0; m < 8; m++)
            acc[m] += sA[(sg * 8 + m) * DD + k] * w;
    }

#pragma unroll
    for (int m = 0; m < 8; m++) {
        int node = base + sg * 8 + m;
        if (node < n) xout[(size_t)node * DD + j] = fmaxf(acc[m], 0.f);
    }
}

// ---------------- FC partial: per-block 16 partial dot products ------------------
__global__ void k_fc_partial(const float* __restrict__ x, const float* __restrict__ fcw, int nd) {
    float acc[OUTN];
#pragma unroll
    for (int j = 0; j < OUTN; j++) acc[j] = 0.f;

    int stride = gridDim.x * blockDim.x;
    for (int i = blockIdx.x * blockDim.x + threadIdx.x; i < nd; i += stride) {
        float xi = fmaxf(x[i], 0.f);
#pragma unroll
        for (int j = 0; j < OUTN; j++)
            acc[j] += fcw[(size_t)j * nd + i] * xi;
    }

    __shared__ float red[256];
#pragma unroll
    for (int j = 0; j < OUTN; j++) {
        red[threadIdx.x] = acc[j];
        __syncthreads();
        for (int o = 128; o > 0; o >>= 1) {
            if (threadIdx.x < o) red[threadIdx.x] += red[threadIdx.x + o];
            __syncthreads();
        }
        if (threadIdx.x == 0) g_partial[blockIdx.x * OUTN + j] = red[0];
        __syncthreads();
    }
}

// ---------------- FC final reduction (fixed order, deterministic) ----------------
__global__ void k_fc_final(float* __restrict__ out, const float* __restrict__ fcb) {
    int j = threadIdx.x >> 5;
    int lane = threadIdx.x & 31;
    if (j < OUTN) {
        float s = 0.f;
        for (int b = lane; b < FCB; b += 32) s += g_partial[b * OUTN + j];
#pragma unroll
        for (int o = 16; o > 0; o >>= 1) s += __shfl_down_sync(0xffffffffu, s, o);
        if (lane == 0) out[j] = s + fcb[j];
    }
}

// ---------------- launcher -------------------------------------------------------
extern "C" void kernel_launch(void* const* d_in, const int* in_sizes, int n_in,
                              void* d_out, int out_size) {
    const float* F     = (const float*)d_in[0];
    const int*   src   = (const int*)d_in[1];
    const int*   dst   = (const int*)d_in[2];
    const float* gcn_w = (const float*)d_in[3];
    const float* gcn_b = (const float*)d_in[4];
    const float* fc_w  = (const float*)d_in[5];
    const float* fc_b  = (const float*)d_in[6];
    float* out = (float*)d_out;

    int n = in_sizes[0] / DD;
    int e = in_sizes[1];
    int nd = n * DD;

    float *x0, *x1, *agg;
    cudaGetSymbolAddress((void**)&x0,  g_x0);
    cudaGetSymbolAddress((void**)&x1,  g_x1);
    cudaGetSymbolAddress((void**)&agg, g_agg);

    int nb_n = (n + 255) / 256;
    int nb_e = (e + 255) / 256;

    // graph build
    k_init_deg<<<nb_n, 256>>>(n);
    k_count<<<nb_e, 256>>>(src, dst, e);
    k_norm<<<nb_n, 256>>>(n);
    k_scan<<<1, 1024>>>(n, e);
    k_scatter<<<nb_e, 256>>>(src, dst, e);

    int gemm_blocks = (n + 31) / 32;
    int spmm_blocks = 2048;

    // layer 0: F -> x0
    k_spmm<<<spmm_blocks, 256>>>(F, agg, n);
    k_gemm<<<gemm_blocks, 256>>>(agg, x0, gcn_w + 0 * DD * DD, gcn_b + 0 * DD, n);
    // layer 1: x0 -> x1
    k_spmm<<<spmm_blocks, 256>>>(x0, agg, n);
    k_gemm<<<gemm_blocks, 256>>>(agg, x1, gcn_w + 1 * DD * DD, gcn_b + 1 * DD, n);
    // layer 2: x1 -> x0
    k_spmm<<<spmm_blocks, 256>>>(x1, agg, n);
    k_gemm<<<gemm_blocks, 256>>>(agg, x0, gcn_w + 2 * DD * DD, gcn_b + 2 * DD, n);

    // final FC
    k_fc_partial<<<FCB, 256>>>(x0, fc_w, nd);
    k_fc_final<<<1, OUTN * 32>>>(out, fc_b);
}

// round 2
// speedup vs baseline: 1.3010x; 1.3010x over previous
#include <cuda_runtime.h>

#define NN   50000
#define DD   64
#define LL   3
#define OUTN 16
#define EE   800000
#define FCB  1024   // blocks for FC partial reduction
#define SCB  256    // scan block size
#define NB_SCAN ((NN + SCB - 1) / SCB)   // 196

// ---------------- static device scratch (no allocations allowed) ----------------
__device__ int   g_deg_out[NN];
__device__ int   g_deg_in[NN];
__device__ float g_norm_src[NN];
__device__ float g_norm_dst[NN];
__device__ int   g_rowptr[NN + 1];
__device__ int   g_cursor[NN];
__device__ int   g_col[EE];
__device__ int   g_bsum[SCB];     // per-block sums (NB_SCAN <= 256)
__device__ int   g_boff[SCB];     // exclusive block offsets
__device__ float g_x0[NN * DD];
__device__ float g_x1[NN * DD];
__device__ float g_agg[NN * DD];
__device__ float g_partial[FCB * OUTN];

// ---------------- degree zero-init (edge-only counts) ----------------------------
__global__ void k_init_deg(int n) {
    int i = blockIdx.x * blockDim.x + threadIdx.x;
    if (i < n) { g_deg_out[i] = 0; g_deg_in[i] = 0; }
}

// ---------------- edge degree histogram (int atomics) ----------------------------
__global__ void k_count(const int* __restrict__ src, const int* __restrict__ dst, int e) {
    int i = blockIdx.x * blockDim.x + threadIdx.x;
    if (i < e) {
        atomicAdd(&g_deg_out[src[i]], 1);
        atomicAdd(&g_deg_in[dst[i]], 1);
    }
}

// self-loop adds 1 to each degree
__global__ void k_norm(int n) {
    int i = blockIdx.x * blockDim.x + threadIdx.x;
    if (i < n) {
        g_norm_src[i] = rsqrtf((float)(g_deg_out[i] + 1));
        g_norm_dst[i] = rsqrtf((float)(g_deg_in[i] + 1));
    }
}

// ---------------- 3-pass parallel exclusive scan of deg_in -> rowptr --------------
__global__ void k_scan_bsum(int n) {
    __shared__ int s[SCB];
    int b = blockIdx.x, t = threadIdx.x;
    int i = b * SCB + t;
    int v = (i < n) ? g_deg_in[i] : 0;
    s[t] = v;
    __syncthreads();
    for (int off = 128; off > 0; off >>= 1) {
        if (t < off) s[t] += s[t + off];
        __syncthreads();
    }
    if (t == 0) g_bsum[b] = s[0];
}

__global__ void k_scan_bsums(int nb) {
    __shared__ int s[SCB];
    int t = threadIdx.x;
    int v = (t < nb) ? g_bsum[t] : 0;
    s[t] = v;
    __syncthreads();
    for (int off = 1; off < SCB; off <<= 1) {
        int u = (t >= off) ? s[t - off] : 0;
        __syncthreads();
        s[t] += u;
        __syncthreads();
    }
    if (t < nb) g_boff[t] = s[t] - v;   // exclusive
}

__global__ void k_scan_final(int n, int e) {
    __shared__ int s[SCB];
    int b = blockIdx.x, t = threadIdx.x;
    int i = b * SCB + t;
    int v = (i < n) ? g_deg_in[i] : 0;
    s[t] = v;
    __syncthreads();
    for (int off = 1; off < SCB; off <<= 1) {
        int u = (t >= off) ? s[t - off] : 0;
        __syncthreads();
        s[t] += u;
        __syncthreads();
    }
    int ex = s[t] - v + g_boff[b];
    if (i < n) { g_rowptr[i] = ex; g_cursor[i] = ex; }
    if (b == 0 && t == 0) g_rowptr[n] = e;
}

// ---------------- CSR scatter (by dst) -------------------------------------------
__global__ void k_scatter(const int* __restrict__ src, const int* __restrict__ dst, int e) {
    int i = blockIdx.x * blockDim.x + threadIdx.x;
    if (i < e) {
        int d = dst[i];
        int pos = atomicAdd(&g_cursor[d], 1);
        g_col[pos] = src[i];
    }
}

// ---------------- SpMM: agg[n] = norm_dst[n] * sum_{s in in(n)} x[s]*norm_src[s] --
// Warp per node (exact launch), float2 per lane, 4-way edge unroll for MLP.
__global__ void k_spmm(const float* __restrict__ xin, float* __restrict__ aggout, int n) {
    int gw = (blockIdx.x * blockDim.x + threadIdx.x) >> 5;
    int lane = threadIdx.x & 31;
    if (gw >= n) return;
    int node = gw;

    int rs = g_rowptr[node];
    int re = g_rowptr[node + 1];

    float2 v = ((const float2*)(xin + (size_t)node * DD))[lane];
    float ns = g_norm_src[node];
    float ax = v.x * ns;   // self loop
    float ay = v.y * ns;

    int ee = rs;
    for (; ee + 4 <= re; ee += 4) {
        int s0 = g_col[ee + 0];
        int s1 = g_col[ee + 1];
        int s2 = g_col[ee + 2];
        int s3 = g_col[ee + 3];
        float w0 = g_norm_src[s0];
        float w1 = g_norm_src[s1];
        float w2 = g_norm_src[s2];
        float w3 = g_norm_src[s3];
        float2 v0 = ((const float2*)(xin + (size_t)s0 * DD))[lane];
        float2 v1 = ((const float2*)(xin + (size_t)s1 * DD))[lane];
        float2 v2 = ((const float2*)(xin + (size_t)s2 * DD))[lane];
        float2 v3 = ((const float2*)(xin + (size_t)s3 * DD))[lane];
        ax += v0.x * w0 + v1.x * w1 + v2.x * w2 + v3.x * w3;
        ay += v0.y * w0 + v1.y * w1 + v2.y * w2 + v3.y * w3;
    }
    for (; ee < re; ee++) {
        int s0 = g_col[ee];
        float w0 = g_norm_src[s0];
        float2 v0 = ((const float2*)(xin + (size_t)s0 * DD))[lane];
        ax += v0.x * w0;
        ay += v0.y * w0;
    }

    float nd = g_norm_dst[node];
    float2 o; o.x = ax * nd; o.y = ay * nd;
    ((float2*)(aggout + (size_t)node * DD))[lane] = o;
}

// ---------------- dense: xout = relu(agg @ W + b) --------------------------------
__global__ void k_gemm(const float* __restrict__ agg, float* __restrict__ xout,
                       const float* __restrict__ W, const float* __restrict__ B, int n) {
    __shared__ float sW[DD * DD];
    __shared__ float sB[DD];
    __shared__ float sA[32 * DD];

    int tid = threadIdx.x;
    for (int i = tid; i < DD * DD; i += 256) sW[i] = W[i];
    if (tid < DD) sB[tid] = B[tid];

    int j  = tid & 63;
    int sg = tid >> 6;

    int base = blockIdx.x * 32;
    __syncthreads();
    for (int i = tid; i < 32 * DD; i += 256) {
        int node = base + (i >> 6);
        sA[i] = (node < n) ? agg[(size_t)base * DD + i] : 0.f;
    }
    __syncthreads();

    float acc[8];
#pragma unroll
    for (int m = 0; m < 8; m++) acc[m] = sB[j];

#pragma unroll 4
    for (int k = 0; k < DD; k++) {
        float w = sW[k * DD + j];
#pragma unroll
        for (int m = 0; m < 8; m++)
            acc[m] += sA[(sg * 8 + m) * DD + k] * w;
    }

#pragma unroll
    for (int m = 0; m < 8; m++) {
        int node = base + sg * 8 + m;
        if (node < n) xout[(size_t)node * DD + j] = fmaxf(acc[m], 0.f);
    }
}

// ---------------- FC partial: float4, 16 partial dots per block -------------------
__global__ void k_fc_partial(const float* __restrict__ x, const float* __restrict__ fcw, int nd) {
    float acc[OUTN];
#pragma unroll
    for (int j = 0; j < OUTN; j++) acc[j] = 0.f;

    int nv = nd >> 2;
    const float4* x4 = (const float4*)x;
    int stride = gridDim.x * blockDim.x;
    for (int i = blockIdx.x * blockDim.x + threadIdx.x; i < nv; i += stride) {
        float4 xv = x4[i];   // x already ReLU'd by k_gemm
#pragma unroll
        for (int j = 0; j < OUTN; j++) {
            float4 w = ((const float4*)(fcw + (size_t)j * nd))[i];
            acc[j] += w.x * xv.x + w.y * xv.y + w.z * xv.z + w.w * xv.w;
        }
    }

    __shared__ float red[256];
#pragma unroll
    for (int j = 0; j < OUTN; j++) {
        red[threadIdx.x] = acc[j];
        __syncthreads();
        for (int o = 128; o > 0; o >>= 1) {
            if (threadIdx.x < o) red[threadIdx.x] += red[threadIdx.x + o];
            __syncthreads();
        }
        if (threadIdx.x == 0) g_partial[blockIdx.x * OUTN + j] = red[0];
        __syncthreads();
    }
}

// ---------------- FC final reduction (fixed order, deterministic) -----------------
__global__ void k_fc_final(float* __restrict__ out, const float* __restrict__ fcb) {
    int j = threadIdx.x >> 5;
    int lane = threadIdx.x & 31;
    if (j < OUTN) {
        float s = 0.f;
        for (int b = lane; b < FCB; b += 32) s += g_partial[b * OUTN + j];
#pragma unroll
        for (int o = 16; o > 0; o >>= 1) s += __shfl_down_sync(0xffffffffu, s, o);
        if (lane == 0) out[j] = s + fcb[j];
    }
}

// ---------------- launcher --------------------------------------------------------
extern "C" void kernel_launch(void* const* d_in, const int* in_sizes, int n_in,
                              void* d_out, int out_size) {
    const float* F     = (const float*)d_in[0];
    const int*   src   = (const int*)d_in[1];
    const int*   dst   = (const int*)d_in[2];
    const float* gcn_w = (const float*)d_in[3];
    const float* gcn_b = (const float*)d_in[4];
    const float* fc_w  = (const float*)d_in[5];
    const float* fc_b  = (const float*)d_in[6];
    float* out = (float*)d_out;

    int n = in_sizes[0] / DD;
    int e = in_sizes[1];
    int nd = n * DD;

    float *x0, *x1, *agg;
    cudaGetSymbolAddress((void**)&x0,  g_x0);
    cudaGetSymbolAddress((void**)&x1,  g_x1);
    cudaGetSymbolAddress((void**)&agg, g_agg);

    int nb_n = (n + 255) / 256;
    int nb_e = (e + 255) / 256;
    int nb_scan = (n + SCB - 1) / SCB;

    // graph build
    k_init_deg<<<nb_n, 256>>>(n);
    k_count<<<nb_e, 256>>>(src, dst, e);
    k_norm<<<nb_n, 256>>>(n);
    k_scan_bsum<<<nb_scan, SCB>>>(n);
    k_scan_bsums<<<1, SCB>>>(nb_scan);
    k_scan_final<<<nb_scan, SCB>>>(n, e);
    k_scatter<<<nb_e, 256>>>(src, dst, e);

    int gemm_blocks = (n + 31) / 32;
    int spmm_blocks = (n * 32 + 255) / 256;   // exact warp-per-node

    // layer 0: F -> x0
    k_spmm<<<spmm_blocks, 256>>>(F, agg, n);
    k_gemm<<<gemm_blocks, 256>>>(agg, x0, gcn_w + 0 * DD * DD, gcn_b + 0 * DD, n);
    // layer 1: x0 -> x1
    k_spmm<<<spmm_blocks, 256>>>(x0, agg, n);
    k_gemm<<<gemm_blocks, 256>>>(agg, x1, gcn_w + 1 * DD * DD, gcn_b + 1 * DD, n);
    // layer 2: x1 -> x0
    k_spmm<<<spmm_blocks, 256>>>(x1, agg, n);
    k_gemm<<<gemm_blocks, 256>>>(agg, x0, gcn_w + 2 * DD * DD, gcn_b + 2 * DD, n);

    // final FC
    k_fc_partial<<<FCB, 256>>>(x0, fc_w, nd);
    k_fc_final<<<1, OUTN * 32>>>(out, fc_b);
}

// round 5
// speedup vs baseline: 1.4546x; 1.1181x over previous
#include <cuda_runtime.h>

#define NN   50000
#define DD   64
#define OUTN 16
#define EE   800000
#define FCB  1024
#define SCB  256
#define NB_SCAN ((NN + SCB - 1) / SCB)

// ---------------- static device scratch ----------------
__device__ int   g_deg_out[NN];
__device__ int   g_deg_in[NN];
__device__ float g_norm_src[NN];
__device__ float g_norm_dst[NN];
__device__ int   g_rowptr[NN + 1];
__device__ int   g_cursor[NN];
__device__ int   g_col[EE];
__device__ float g_xs[NN * DD];    // norm_src-prescaled activations (SpMM input)
__device__ float g_agg[NN * DD];   // SpMM output / GEMM input
__device__ float g_x[NN * DD];     // final layer raw output (FC input)
__device__ float g_partial[FCB * OUTN];

// ---------------- edge degree histogram (deg arrays are zero on entry;
// zeroed after use by k_scatter_scale, so invariant holds across replays) ----
__global__ void k_count(const int* __restrict__ src, const int* __restrict__ dst, int e) {
    int i = blockIdx.x * blockDim.x + threadIdx.x;
    if (i < e) {
        atomicAdd(&g_deg_out[src[i]], 1);
        atomicAdd(&g_deg_in[dst[i]], 1);
    }
}

// ---------------- fused scan + norm: each block redundantly computes its
// prefix base by summing deg_in[0, b*256), then local scan; also computes
// norms (self loop -> +1). ----------------------------------------------------
__global__ void k_scan_norm(int n, int e) {
    __shared__ int red[SCB];
    int b = blockIdx.x, t = threadIdx.x;
    int start = b * SCB;

    // 1) base = sum deg_in[0, start)
    int s = 0;
    for (int i = t; i < start; i += SCB) s += g_deg_in[i];
    red[t] = s;
    __syncthreads();
    for (int off = 128; off > 0; off >>= 1) {
        if (t < off) red[t] += red[t + off];
        __syncthreads();
    }
    int base = red[0];
    __syncthreads();

    // 2) local inclusive scan of this block's 256 degrees
    int i = start + t;
    int v = (i < n) ? g_deg_in[i] : 0;
    red[t] = v;
    __syncthreads();
    for (int off = 1; off < SCB; off <<= 1) {
        int u = (t >= off) ? red[t - off] : 0;
        __syncthreads();
        red[t] += u;
        __syncthreads();
    }
    int ex = base + red[t] - v;
    if (i < n) {
        g_rowptr[i] = ex;
        g_cursor[i] = ex;
        g_norm_src[i] = rsqrtf((float)(g_deg_out[i] + 1));
        g_norm_dst[i] = rsqrtf((float)(v + 1));
    }
    if (b == 0 && t == 0) g_rowptr[n] = e;
}

// ---------------- CSR scatter + F prescale + deg re-zero ---------------------
__global__ void k_scatter_scale(const int* __restrict__ src, const int* __restrict__ dst,
                                const float* __restrict__ F, int e, int n) {
    int i = blockIdx.x * blockDim.x + threadIdx.x;
    if (i < e) {
        int d = dst[i];
        int pos = atomicAdd(&g_cursor[d], 1);
        g_col[pos] = src[i];
    }
    if (i < n) { g_deg_in[i] = 0; g_deg_out[i] = 0; }
    if (i < n * (DD / 4)) {   // prescale F by norm_src -> xs (float4 granules)
        int node = i >> 4;
        float ns = g_norm_src[node];
        float4 v = ((const float4*)F)[i];
        v.x *= ns; v.y *= ns; v.z *= ns; v.w *= ns;
        ((float4*)g_xs)[i] = v;
    }
}

// ---------------- SpMM: agg[n] = norm_dst[n] * (xs[n] + sum_{s in in(n)} xs[s]) --
// Warp per node; half-warps each process one edge with float4 lanes (16 lanes
// cover the 256B row). 4-pair unroll = 8 edges per iteration.
__global__ void k_spmm(const float* __restrict__ xs, float* __restrict__ agg, int n) {
    int gw = (blockIdx.x * blockDim.x + threadIdx.x) >> 5;
    if (gw >= n) return;
    int lane = threadIdx.x & 31;
    int half = lane >> 4;     // 0 or 1
    int q    = lane & 15;     // float4 index within row

    int rs = g_rowptr[gw];
    int re = g_rowptr[gw + 1];

    float4 acc;
    if (half == 0) acc = ((const float4*)(xs + (size_t)gw * DD))[q];   // self loop
    else           acc = make_float4(0.f, 0.f, 0.f, 0.f);

    int ee = rs;
    for (; ee + 8 <= re; ee += 8) {
        int s0 = g_col[ee + half + 0];
        int s1 = g_col[ee + half + 2];
        int s2 = g_col[ee + half + 4];
        int s3 = g_col[ee + half + 6];
        float4 v0 = ((const float4*)(xs + (size_t)s0 * DD))[q];
        float4 v1 = ((const float4*)(xs + (size_t)s1 * DD))[q];
        float4 v2 = ((const float4*)(xs + (size_t)s2 * DD))[q];
        float4 v3 = ((const float4*)(xs + (size_t)s3 * DD))[q];
        acc.x += v0.x + v1.x + v2.x + v3.x;
        acc.y += v0.y + v1.y + v2.y + v3.y;
        acc.z += v0.z + v1.z + v2.z + v3.z;
        acc.w += v0.w + v1.w + v2.w + v3.w;
    }
    for (; ee + 2 <= re; ee += 2) {
        int s0 = g_col[ee + half];
        float4 v0 = ((const float4*)(xs + (size_t)s0 * DD))[q];
        acc.x += v0.x; acc.y += v0.y; acc.z += v0.z; acc.w += v0.w;
    }
    if (ee < re && half == 0) {
        int s0 = g_col[ee];
        float4 v0 = ((const float4*)(xs + (size_t)s0 * DD))[q];
        acc.x += v0.x; acc.y += v0.y; acc.z += v0.z; acc.w += v0.w;
    }

    // combine the two half-warp partials
    acc.x += __shfl_xor_sync(0xffffffffu, acc.x, 16);
    acc.y += __shfl_xor_sync(0xffffffffu, acc.y, 16);
    acc.z += __shfl_xor_sync(0xffffffffu, acc.z, 16);
    acc.w += __shfl_xor_sync(0xffffffffu, acc.w, 16);

    if (half == 0) {
        float nd = g_norm_dst[gw];
        acc.x *= nd; acc.y *= nd; acc.z *= nd; acc.w *= nd;
        ((float4*)(agg + (size_t)gw * DD))[q] = acc;
    }
}

// ---------------- dense: out = relu(agg @ W + b) [* norm_src if scale_out] ------
// 64-node tile, 256 threads. Each thread: 2 j's (j, j+32) x 8 nodes.
// float4 k-vectorized sA loads -> FMA-bound inner loop.
__global__ void k_gemm(const float* __restrict__ agg, float* __restrict__ xout,
                       const float* __restrict__ W, const float* __restrict__ B,
                       int n, int scale_out) {
    __shared__ float sW[DD * DD];
    __shared__ float sB[DD];
    __shared__ float sA[64 * DD];

    int tid = threadIdx.x;
    for (int i = tid; i < DD * DD; i += 256) sW[i] = W[i];
    if (tid < DD) sB[tid] = B[tid];

    int base = blockIdx.x * 64;
    // load 64x64 agg tile (float4 granules)
    int gmax = n * (DD / 4);
    for (int i = tid; i < 64 * (DD / 4); i += 256) {
        int gi = base * (DD / 4) + i;
        float4 v = (gi < gmax) ? ((const float4*)agg)[gi] : make_float4(0.f, 0.f, 0.f, 0.f);
        ((float4*)sA)[i] = v;
    }
    __syncthreads();

    int j  = tid & 31;        // output features j and j+32
    int sg = tid >> 5;        // node subgroup (8 groups x 8 nodes)

    float acc0[8], acc1[8];
#pragma unroll
    for (int m = 0; m < 8; m++) { acc0[m] = sB[j]; acc1[m] = sB[j + 32]; }

#pragma unroll
    for (int k4 = 0; k4 < DD / 4; k4++) {
        float w0[4], w1[4];
#pragma unroll
        for (int kk = 0; kk < 4; kk++) {
            w0[kk] = sW[(k4 * 4 + kk) * DD + j];
            w1[kk] = sW[(k4 * 4 + kk) * DD + j + 32];
        }
#pragma unroll
        for (int m = 0; m < 8; m++) {
            float4 a = ((const float4*)(sA + (sg * 8 + m) * DD))[k4];
            acc0[m] += a.x * w0[0] + a.y * w0[1] + a.z * w0[2] + a.w * w0[3];
            acc1[m] += a.x * w1[0] + a.y * w1[1] + a.z * w1[2] + a.w * w1[3];
        }
    }

#pragma unroll
    for (int m = 0; m < 8; m++) {
        int node = base + sg * 8 + m;
        if (node < n) {
            float sc = scale_out ? g_norm_src[node] : 1.f;
            xout[(size_t)node * DD + j]      = fmaxf(acc0[m], 0.f) * sc;
            xout[(size_t)node * DD + j + 32] = fmaxf(acc1[m], 0.f) * sc;
        }
    }
}

// ---------------- FC partial: float4, 16 partial dots per block ------------------
__global__ void k_fc_partial(const float* __restrict__ x, const float* __restrict__ fcw, int nd) {
    float acc[OUTN];
#pragma unroll
    for (int j = 0; j < OUTN; j++) acc[j] = 0.f;

    int nv = nd >> 2;
    const float4* x4 = (const float4*)x;
    int stride = gridDim.x * blockDim.x;
    for (int i = blockIdx.x * blockDim.x + threadIdx.x; i < nv; i += stride) {
        float4 xv = x4[i];   // already ReLU'd by k_gemm
#pragma unroll
        for (int j = 0; j < OUTN; j++) {
            float4 w = ((const float4*)(fcw + (size_t)j * nd))[i];
            acc[j] += w.x * xv.x + w.y * xv.y + w.z * xv.z + w.w * xv.w;
        }
    }

    __shared__ float red[256];
#pragma unroll
    for (int j = 0; j < OUTN; j++) {
        red[threadIdx.x] = acc[j];
        __syncthreads();
        for (int o = 128; o > 0; o >>= 1) {
            if (threadIdx.x < o) red[threadIdx.x] += red[threadIdx.x + o];
            __syncthreads();
        }
        if (threadIdx.x == 0) g_partial[blockIdx.x * OUTN + j] = red[0];
        __syncthreads();
    }
}

// ---------------- FC final reduction ---------------------------------------------
__global__ void k_fc_final(float* __restrict__ out, const float* __restrict__ fcb) {
    int j = threadIdx.x >> 5;
    int lane = threadIdx.x & 31;
    if (j < OUTN) {
        float s = 0.f;
        for (int b = lane; b < FCB; b += 32) s += g_partial[b * OUTN + j];
#pragma unroll
        for (int o = 16; o > 0; o >>= 1) s += __shfl_down_sync(0xffffffffu, s, o);
        if (lane == 0) out[j] = s + fcb[j];
    }
}

// ---------------- launcher --------------------------------------------------------
extern "C" void kernel_launch(void* const* d_in, const int* in_sizes, int n_in,
                              void* d_out, int out_size) {
    const float* F     = (const float*)d_in[0];
    const int*   src   = (const int*)d_in[1];
    const int*   dst   = (const int*)d_in[2];
    const float* gcn_w = (const float*)d_in[3];
    const float* gcn_b = (const float*)d_in[4];
    const float* fc_w  = (const float*)d_in[5];
    const float* fc_b  = (const float*)d_in[6];
    float* out = (float*)d_out;

    int n = in_sizes[0] / DD;
    int e = in_sizes[1];
    int nd = n * DD;

    float *xs, *agg, *x;
    cudaGetSymbolAddress((void**)&xs,  g_xs);
    cudaGetSymbolAddress((void**)&agg, g_agg);
    cudaGetSymbolAddress((void**)&x,   g_x);

    int nb_e = (e + 255) / 256;
    int nb_scan = (n + SCB - 1) / SCB;
    int spmm_blocks = (n * 32 + 255) / 256;
    int gemm_blocks = (n + 63) / 64;

    // graph build (3 launches)
    k_count<<<nb_e, 256>>>(src, dst, e);
    k_scan_norm<<<nb_scan, SCB>>>(n, e);
    k_scatter_scale<<<nb_e, 256>>>(src, dst, F, e, n);

    // layer 0
    k_spmm<<<spmm_blocks, 256>>>(xs, agg, n);                                    // launch #4 (profiled)
    k_gemm<<<gemm_blocks, 256>>>(agg, xs, gcn_w + 0 * DD * DD, gcn_b + 0 * DD, n, 1);
    // layer 1
    k_spmm<<<spmm_blocks, 256>>>(xs, agg, n);
    k_gemm<<<gemm_blocks, 256>>>(agg, xs, gcn_w + 1 * DD * DD, gcn_b + 1 * DD, n, 1);
    // layer 2 (raw output for FC)
    k_spmm<<<spmm_blocks, 256>>>(xs, agg, n);
    k_gemm<<<gemm_blocks, 256>>>(agg, x, gcn_w + 2 * DD * DD, gcn_b + 2 * DD, n, 0);

    // final FC
    k_fc_partial<<<FCB, 256>>>(x, fc_w, nd);
    k_fc_final<<<1, OUTN * 32>>>(out, fc_b);
}